// round 15
// baseline (speedup 1.0000x reference)
#include <cuda_runtime.h>
#include <cuda_fp16.h>

#define NN 100000
#define NE 2500000
#define NG 1000
#define HD 32
#define SCAN_B 512
#define NB ((NN + SCAN_B - 1) / SCAN_B)   // 196

// ---- scratch (__device__ globals; allocation-free) ----
__device__ int   g_is64;
__device__ __align__(16) float  g_deg[NN];        // dinv (written by k_prep)
__device__ __align__(16) int    g_cnt[NN];
__device__ __align__(16) int    g_scani[NN];
__device__ __align__(16) int    g_bsum[256];
__device__ __align__(16) int    g_off[NN];
__device__ __align__(16) int    g_cur[NN];
__device__ __align__(16) int2   g_csr[NE];        // {src, packed half2{w,w}}
__device__ __align__(16) float4 g_x[NN];          // dinv[i] * x[i]
__device__ __align__(16) __half g_Bh[NN * HD];    // fp16 prescaled h1@W2
__device__ __align__(16) float4 g_P[NN];          // dv_i * (relu(h2) @ (W3@lin_w)), 3 used
__device__ __align__(16) float  g_gsum[NG * 4];   // pooled 3-dim sums (padded 4)
__device__ __align__(16) float  g_gcnt[NG];

__device__ __forceinline__ int ldidx(const void* p, long long e) {
    if (g_is64) return (int)((const long long*)p)[e];
    return ((const int*)p)[e];
}

__global__ void k_init(const void* ei) {
    int t = blockIdx.x * blockDim.x + threadIdx.x;
    if (t == 0) {
        const int* p = (const int*)ei;
        int z = 0;
#pragma unroll
        for (int j = 1; j < 64; j += 2) z |= p[j];
        g_is64 = (z == 0) ? 1 : 0;
    }
    if (t < NN) g_cnt[t] = 0;
    if (t < NG * 4) g_gsum[t] = 0.f;
    if (t < NG) g_gcnt[t] = 0.f;
}

__global__ void k_hist(const void* __restrict__ ei) {
    int e = blockIdx.x * blockDim.x + threadIdx.x;
    if (e >= NE) return;
    int c = ldidx(ei, (long long)NE + e);
    atomicAdd(&g_cnt[c], 1);
}

__global__ void k_scan1() {
    __shared__ int s[SCAN_B];
    int tid = threadIdx.x;
    int i = blockIdx.x * SCAN_B + tid;
    s[tid] = (i < NN) ? g_cnt[i] : 0;
    __syncthreads();
#pragma unroll
    for (int off = 1; off < SCAN_B; off <<= 1) {
        int v = (tid >= off) ? s[tid - off] : 0;
        __syncthreads();
        s[tid] += v;
        __syncthreads();
    }
    if (i < NN) g_scani[i] = s[tid];
    if (tid == SCAN_B - 1) g_bsum[blockIdx.x] = s[tid];
}

// merged scan2+scan3
__global__ void k_scan23() {
    __shared__ int s[256];
    int tid = threadIdx.x;
    s[tid] = (tid < NB) ? g_bsum[tid] : 0;
    __syncthreads();
#pragma unroll
    for (int off = 1; off < 256; off <<= 1) {
        int v = (tid >= off) ? s[tid - off] : 0;
        __syncthreads();
        s[tid] += v;
        __syncthreads();
    }
    int i = blockIdx.x * blockDim.x + tid;
    if (i >= NN) return;
    int b = i / SCAN_B;
    int add = (b > 0) ? s[b - 1] : 0;
    int excl = add + g_scani[i] - g_cnt[i];
    g_off[i] = excl;
    g_cur[i] = excl;
}

// CSR fill: weight packed once as half2{w,w}
__global__ void k_fill(const void* __restrict__ ei, const float* __restrict__ ew) {
    int e = blockIdx.x * blockDim.x + threadIdx.x;
    if (e >= NE) return;
    int r = ldidx(ei, e);
    int c = ldidx(ei, (long long)NE + e);
    int p = atomicAdd(&g_cur[c], 1);
    float w = ew[e];
    __half2 wp = __floats2half2_rn(w, w);
    g_csr[p] = make_int2(r, *reinterpret_cast<int*>(&wp));
}

// warp per node: deg = coalesced bucket sum, dinv, prescale x.
__global__ void k_prep(const float* __restrict__ x) {
    int t = blockIdx.x * blockDim.x + threadIdx.x;
    int i = t >> 5, lane = t & 31;
    if (i >= NN) return;
    int beg = g_off[i];
    int cnt = g_cnt[i];
    float s = 0.f;
    for (int e = lane; e < cnt; e += 32) {
        int wb = g_csr[beg + e].y;
        s += __low2float(*reinterpret_cast<__half2*>(&wb));
    }
#pragma unroll
    for (int d = 1; d < 32; d <<= 1)
        s += __shfl_xor_sync(0xffffffffu, s, d);
    float dv = rsqrtf(s + 1.0f);
    if (lane == 0) {
        g_deg[i] = dv;
        float4 xi = __ldg(&reinterpret_cast<const float4*>(x)[i]);
        g_x[i] = make_float4(dv * xi.x, dv * xi.y, dv * xi.z, dv * xi.w);
    }
}

// Layer 1: gather prescaled 16B fp32 x rows (lane-strided);
// h1 = relu(dv*(sum+self)@W1+b1); store g_Bh[i] = fp16(dv * (h1@W2)).
__global__ void k_layer1(const float* __restrict__ W1, const float* __restrict__ b1,
                         const float* __restrict__ W2) {
    __shared__ float W1s[4 * HD];
    __shared__ float W2s[HD * HD];
    int tid = threadIdx.x;
    for (int k = tid; k < 4 * HD; k += blockDim.x)  W1s[k] = W1[k];
    for (int k = tid; k < HD * HD; k += blockDim.x) W2s[k] = W2[k];
    __syncthreads();
    int t = blockIdx.x * blockDim.x + tid;
    int i = t >> 5, lane = t & 31;
    if (i >= NN) return;

    int beg = g_off[i];
    int cnt = g_cnt[i];
    float4 acc = make_float4(0.f, 0.f, 0.f, 0.f);
    for (int e = lane; e < cnt; e += 32) {
        int2 ce = g_csr[beg + e];
        float w = __low2float(*reinterpret_cast<__half2*>(&ce.y));
        float4 xv = g_x[ce.x];
        acc.x = fmaf(w, xv.x, acc.x);
        acc.y = fmaf(w, xv.y, acc.y);
        acc.z = fmaf(w, xv.z, acc.z);
        acc.w = fmaf(w, xv.w, acc.w);
    }
#pragma unroll
    for (int d = 1; d < 32; d <<= 1) {
        acc.x += __shfl_xor_sync(0xffffffffu, acc.x, d);
        acc.y += __shfl_xor_sync(0xffffffffu, acc.y, d);
        acc.z += __shfl_xor_sync(0xffffffffu, acc.z, d);
        acc.w += __shfl_xor_sync(0xffffffffu, acc.w, d);
    }
    float4 xi = g_x[i];
    float dv = g_deg[i];
    acc.x = (acc.x + xi.x) * dv;
    acc.y = (acc.y + xi.y) * dv;
    acc.z = (acc.z + xi.z) * dv;
    acc.w = (acc.w + xi.w) * dv;

    float h = __ldg(&b1[lane]);
    h = fmaf(acc.x, W1s[0 * HD + lane], h);
    h = fmaf(acc.y, W1s[1 * HD + lane], h);
    h = fmaf(acc.z, W1s[2 * HD + lane], h);
    h = fmaf(acc.w, W1s[3 * HD + lane], h);
    h = fmaxf(h, 0.f);

    float o = 0.f;
#pragma unroll
    for (int k = 0; k < HD; k++) {
        float hk = __shfl_sync(0xffffffffu, h, k);
        o = fmaf(hk, W2s[k * HD + lane], o);
    }
    g_Bh[(size_t)i * HD + lane] = __float2half_rn(dv * o);
}

// HFMA2 fp16 gather (R13 best form): warp = 4 edge-groups x 8 lanes, 8 edges/iter.
__device__ __forceinline__ float4 gather_node_h2(const uint2* __restrict__ src, int i,
                                                 int grp, int sub) {
    int beg = g_off[i];
    int cnt = g_cnt[i];
    const __half2 hz = __floats2half2_rn(0.f, 0.f);
    __half2 a01 = hz, a23 = hz, b01 = hz, b23 = hz;
    int e = 0;
#pragma unroll 2
    for (; e + 8 <= cnt; e += 8) {
        int2 ce0 = g_csr[beg + e + grp];
        int2 ce1 = g_csr[beg + e + 4 + grp];
        __half2 w0 = *reinterpret_cast<__half2*>(&ce0.y);
        __half2 w1 = *reinterpret_cast<__half2*>(&ce1.y);
        uint2 u0 = src[(size_t)ce0.x * 8 + sub];
        uint2 u1 = src[(size_t)ce1.x * 8 + sub];
        a01 = __hfma2(w0, *reinterpret_cast<__half2*>(&u0.x), a01);
        a23 = __hfma2(w0, *reinterpret_cast<__half2*>(&u0.y), a23);
        b01 = __hfma2(w1, *reinterpret_cast<__half2*>(&u1.x), b01);
        b23 = __hfma2(w1, *reinterpret_cast<__half2*>(&u1.y), b23);
    }
    if (e + 4 <= cnt) {
        int2 ce = g_csr[beg + e + grp];
        __half2 w = *reinterpret_cast<__half2*>(&ce.y);
        uint2 u = src[(size_t)ce.x * 8 + sub];
        a01 = __hfma2(w, *reinterpret_cast<__half2*>(&u.x), a01);
        a23 = __hfma2(w, *reinterpret_cast<__half2*>(&u.y), a23);
        e += 4;
    }
    int rem = cnt - e;                           // 0..3
    if (rem > 0) {
        int g2 = min(grp, rem - 1);              // clamp: valid load, zero weight
        int2 ce = g_csr[beg + e + g2];
        int wb = (grp < rem) ? ce.y : 0;
        __half2 w = *reinterpret_cast<__half2*>(&wb);
        uint2 u = src[(size_t)ce.x * 8 + sub];
        a01 = __hfma2(w, *reinterpret_cast<__half2*>(&u.x), a01);
        a23 = __hfma2(w, *reinterpret_cast<__half2*>(&u.y), a23);
    }
    float2 fa01 = __half22float2(a01), fa23 = __half22float2(a23);
    float2 fb01 = __half22float2(b01), fb23 = __half22float2(b23);
    float4 acc = make_float4(fa01.x + fb01.x, fa01.y + fb01.y,
                             fa23.x + fb23.x, fa23.y + fb23.y);
#pragma unroll
    for (int d = 8; d <= 16; d <<= 1) {          // reduce across the 4 groups
        acc.x += __shfl_xor_sync(0xffffffffu, acc.x, d);
        acc.y += __shfl_xor_sync(0xffffffffu, acc.y, d);
        acc.z += __shfl_xor_sync(0xffffffffu, acc.z, d);
        acc.w += __shfl_xor_sync(0xffffffffu, acc.w, d);
    }
    uint2 us = src[(size_t)i * 8 + sub];         // self row (prescaled)
    float2 s01 = __half22float2(*reinterpret_cast<__half2*>(&us.x));
    float2 s23 = __half22float2(*reinterpret_cast<__half2*>(&us.y));
    acc.x += s01.x; acc.y += s01.y; acc.z += s23.x; acc.w += s23.y;
    return acc;
}

// Layer 2: gather g_Bh; v = relu(dv*acc + b2); project to 3 dims with
// M = W3 @ lin_w (aggregation/projection commute, layer 3 has no relu);
// store g_P[i] = float4{dv * (v@M), 0}.
__global__ void k_layer2(const float* __restrict__ bias, const float* __restrict__ W3,
                         const float* __restrict__ lw) {
    __shared__ float Ms[HD * 3];                  // M[k][j] = sum_f W3[k][f]*lw[f][j]
    int tid = threadIdx.x;
    if (tid < HD * 3) {
        int k = tid / 3, j = tid % 3;
        float m = 0.f;
#pragma unroll
        for (int f = 0; f < HD; f++)
            m = fmaf(__ldg(&W3[k * HD + f]), __ldg(&lw[f * 3 + j]), m);
        Ms[tid] = m;
    }
    __syncthreads();
    int t = blockIdx.x * blockDim.x + tid;
    int i = t >> 5, lane = t & 31, grp = lane >> 3, sub = lane & 7;
    if (i >= NN) return;

    float4 v = gather_node_h2(reinterpret_cast<const uint2*>(g_Bh), i, grp, sub);
    float dv = g_deg[i];
    float4 b4 = __ldg(&reinterpret_cast<const float4*>(bias)[sub]);
    v.x = fmaxf(fmaf(v.x, dv, b4.x), 0.f);
    v.y = fmaxf(fmaf(v.y, dv, b4.y), 0.f);
    v.z = fmaxf(fmaf(v.z, dv, b4.z), 0.f);
    v.w = fmaxf(fmaf(v.w, dv, b4.w), 0.f);

    // o_j = sum_k v_k * M[k][j]; lane holds k = 4*sub .. 4*sub+3
    float o0 = 0.f, o1 = 0.f, o2 = 0.f;
    int k0 = sub * 4;
    o0 = fmaf(v.x, Ms[(k0 + 0) * 3 + 0], o0);
    o1 = fmaf(v.x, Ms[(k0 + 0) * 3 + 1], o1);
    o2 = fmaf(v.x, Ms[(k0 + 0) * 3 + 2], o2);
    o0 = fmaf(v.y, Ms[(k0 + 1) * 3 + 0], o0);
    o1 = fmaf(v.y, Ms[(k0 + 1) * 3 + 1], o1);
    o2 = fmaf(v.y, Ms[(k0 + 1) * 3 + 2], o2);
    o0 = fmaf(v.z, Ms[(k0 + 2) * 3 + 0], o0);
    o1 = fmaf(v.z, Ms[(k0 + 2) * 3 + 1], o1);
    o2 = fmaf(v.z, Ms[(k0 + 2) * 3 + 2], o2);
    o0 = fmaf(v.w, Ms[(k0 + 3) * 3 + 0], o0);
    o1 = fmaf(v.w, Ms[(k0 + 3) * 3 + 1], o1);
    o2 = fmaf(v.w, Ms[(k0 + 3) * 3 + 2], o2);
#pragma unroll
    for (int d = 1; d <= 4; d <<= 1) {            // reduce across the 8 sub lanes
        o0 += __shfl_xor_sync(0xffffffffu, o0, d);
        o1 += __shfl_xor_sync(0xffffffffu, o1, d);
        o2 += __shfl_xor_sync(0xffffffffu, o2, d);
    }
    if (lane == 0)
        g_P[i] = make_float4(dv * o0, dv * o1, dv * o2, 0.f);
}

// Layer 3: lane-per-edge gather of 16B P rows + sorted-batch mean-pool (3 dims).
__global__ void k_gather_pool(const void* __restrict__ batch) {
    __shared__ float s[8][4];
    __shared__ int sg[8];
    int tid = threadIdx.x;
    int t = blockIdx.x * blockDim.x + tid;
    int i = t >> 5, lane = t & 31;
    int warpid = tid >> 5;
    int beg = g_off[i];
    int cnt = g_cnt[i];
    float a0 = 0.f, a1 = 0.f, a2 = 0.f;
    for (int e = lane; e < cnt; e += 32) {
        int2 ce = g_csr[beg + e];
        float w = __low2float(*reinterpret_cast<__half2*>(&ce.y));
        float4 p = g_P[ce.x];
        a0 = fmaf(w, p.x, a0);
        a1 = fmaf(w, p.y, a1);
        a2 = fmaf(w, p.z, a2);
    }
#pragma unroll
    for (int d = 1; d < 32; d <<= 1) {
        a0 += __shfl_xor_sync(0xffffffffu, a0, d);
        a1 += __shfl_xor_sync(0xffffffffu, a1, d);
        a2 += __shfl_xor_sync(0xffffffffu, a2, d);
    }
    if (lane == 0) {
        float4 pi = g_P[i];
        float dv = g_deg[i];
        s[warpid][0] = dv * (a0 + pi.x);
        s[warpid][1] = dv * (a1 + pi.y);
        s[warpid][2] = dv * (a2 + pi.z);
        sg[warpid] = ldidx(batch, i);
    }
    __syncthreads();
    if (tid < 3) {
        int g0 = sg[0];
        if (g0 == sg[7]) {                        // sorted => all 8 equal
            float sum = 0.f;
#pragma unroll
            for (int w = 0; w < 8; w++) sum += s[w][tid];
            atomicAdd(&g_gsum[g0 * 4 + tid], sum);
            if (tid == 0) atomicAdd(&g_gcnt[g0], 8.0f);
        } else {
#pragma unroll
            for (int w = 0; w < 8; w++)
                atomicAdd(&g_gsum[sg[w] * 4 + tid], s[w][tid]);
            if (tid == 0) {
#pragma unroll
                for (int w = 0; w < 8; w++) atomicAdd(&g_gcnt[sg[w]], 1.0f);
            }
        }
    }
}

// Head: logits_j = gsum_j/cnt + c_j with c = b3@lin_w + lin_b; softmax.
__global__ void k_head(const float* __restrict__ b3, const float* __restrict__ lw,
                       const float* __restrict__ lb, float* __restrict__ out) {
    int g = blockIdx.x * blockDim.x + threadIdx.x;
    if (g >= NG) return;
    float c0 = __ldg(&lb[0]), c1 = __ldg(&lb[1]), c2 = __ldg(&lb[2]);
#pragma unroll
    for (int f = 0; f < HD; f++) {
        float bf = __ldg(&b3[f]);
        c0 = fmaf(bf, __ldg(&lw[f * 3 + 0]), c0);
        c1 = fmaf(bf, __ldg(&lw[f * 3 + 1]), c1);
        c2 = fmaf(bf, __ldg(&lw[f * 3 + 2]), c2);
    }
    float inv = 1.0f / fmaxf(g_gcnt[g], 1.0f);
    float l0 = g_gsum[g * 4 + 0] * inv + c0;
    float l1 = g_gsum[g * 4 + 1] * inv + c1;
    float l2 = g_gsum[g * 4 + 2] * inv + c2;
    float m = fmaxf(l0, fmaxf(l1, l2));
    float e0 = expf(l0 - m), e1 = expf(l1 - m), e2 = expf(l2 - m);
    float s = 1.0f / (e0 + e1 + e2);
    out[g * 3 + 0] = e0 * s;
    out[g * 3 + 1] = e1 * s;
    out[g * 3 + 2] = e2 * s;
}

extern "C" void kernel_launch(void* const* d_in, const int* in_sizes, int n_in,
                              void* d_out, int out_size) {
    const float* x     = (const float*)d_in[0];
    const void*  ei    = d_in[1];
    const float* ew    = (const float*)d_in[2];
    const void*  batch = d_in[3];
    const float* W1    = (const float*)d_in[4];
    const float* b1    = (const float*)d_in[5];
    const float* W2    = (const float*)d_in[6];
    const float* b2    = (const float*)d_in[7];
    const float* W3    = (const float*)d_in[8];
    const float* b3    = (const float*)d_in[9];
    const float* lw    = (const float*)d_in[10];
    const float* lb    = (const float*)d_in[11];
    float* out = (float*)d_out;

    const int B = 256;
    const int gbN  = (NN + B - 1) / B;
    const int gbE  = (NE + B - 1) / B;
    const int gbNH = (NN * HD) / B;           // 12500 blocks, 8 nodes each

    k_init<<<gbN, B>>>(ei);
    k_hist<<<gbE, B>>>(ei);
    k_scan1<<<NB, SCAN_B>>>();
    k_scan23<<<gbN, B>>>();
    k_fill<<<gbE, B>>>(ei, ew);
    k_prep<<<gbNH, B>>>(x);

    k_layer1<<<gbNH, B>>>(W1, b1, W2);        // gather g_x -> g_Bh (fp16)
    k_layer2<<<gbNH, B>>>(b2, W3, lw);        // gather g_Bh -> g_P (3-dim, fp32)
    k_gather_pool<<<gbNH, B>>>(batch);        // 16B-row gather g_P + pool
    k_head<<<(NG + B - 1) / B, B>>>(b3, lw, lb, out);
}

// round 16
// speedup vs baseline: 1.2450x; 1.2450x over previous
#include <cuda_runtime.h>
#include <cuda_fp16.h>

#define NN 100000
#define NE 2500000
#define NG 1000
#define HD 32
#define SCAN_B 512
#define NB ((NN + SCAN_B - 1) / SCAN_B)   // 196

// ---- scratch (__device__ globals; allocation-free) ----
__device__ int   g_is64;
__device__ __align__(16) float  g_M[HD * 3];      // W3 @ lin_w (computed once in k_init)
__device__ __align__(16) float  g_deg[NN];        // dinv (written by k_prep)
__device__ __align__(16) int    g_cnt[NN];
__device__ __align__(16) int    g_scani[NN];
__device__ __align__(16) int    g_bsum[256];
__device__ __align__(16) int    g_off[NN];
__device__ __align__(16) int    g_cur[NN];
__device__ __align__(16) int2   g_csr[NE];        // {src, packed half2{w,w}}
__device__ __align__(16) float4 g_x[NN];          // dinv[i] * x[i]
__device__ __align__(16) __half g_Bh[NN * HD];    // fp16 prescaled h1@W2
__device__ __align__(16) float4 g_P[NN];          // dv_i * (relu(h2)@M), 3 used
__device__ __align__(16) float  g_gsum[NG * 4];   // pooled 3-dim sums (padded 4)
__device__ __align__(16) float  g_gcnt[NG];

__device__ __forceinline__ int ldidx(const void* p, long long e) {
    if (g_is64) return (int)((const long long*)p)[e];
    return ((const int*)p)[e];
}

// init + index-width detect + ONE-TIME M = W3@lin_w (block 0, threads 0..95)
__global__ void k_init(const void* ei, const float* __restrict__ W3,
                       const float* __restrict__ lw) {
    int t = blockIdx.x * blockDim.x + threadIdx.x;
    if (t == 0) {
        const int* p = (const int*)ei;
        int z = 0;
#pragma unroll
        for (int j = 1; j < 64; j += 2) z |= p[j];
        g_is64 = (z == 0) ? 1 : 0;
    }
    if (blockIdx.x == 0 && threadIdx.x < HD * 3) {
        int k = threadIdx.x / 3, j = threadIdx.x % 3;
        float m = 0.f;
#pragma unroll
        for (int f = 0; f < HD; f++)
            m = fmaf(__ldg(&W3[k * HD + f]), __ldg(&lw[f * 3 + j]), m);
        g_M[threadIdx.x] = m;
    }
    if (t < NN) g_cnt[t] = 0;
    if (t < NG * 4) g_gsum[t] = 0.f;
    if (t < NG) g_gcnt[t] = 0.f;
}

__global__ void k_hist(const void* __restrict__ ei) {
    int e = blockIdx.x * blockDim.x + threadIdx.x;
    if (e >= NE) return;
    int c = ldidx(ei, (long long)NE + e);
    atomicAdd(&g_cnt[c], 1);
}

__global__ void k_scan1() {
    __shared__ int s[SCAN_B];
    int tid = threadIdx.x;
    int i = blockIdx.x * SCAN_B + tid;
    s[tid] = (i < NN) ? g_cnt[i] : 0;
    __syncthreads();
#pragma unroll
    for (int off = 1; off < SCAN_B; off <<= 1) {
        int v = (tid >= off) ? s[tid - off] : 0;
        __syncthreads();
        s[tid] += v;
        __syncthreads();
    }
    if (i < NN) g_scani[i] = s[tid];
    if (tid == SCAN_B - 1) g_bsum[blockIdx.x] = s[tid];
}

// merged scan2+scan3
__global__ void k_scan23() {
    __shared__ int s[256];
    int tid = threadIdx.x;
    s[tid] = (tid < NB) ? g_bsum[tid] : 0;
    __syncthreads();
#pragma unroll
    for (int off = 1; off < 256; off <<= 1) {
        int v = (tid >= off) ? s[tid - off] : 0;
        __syncthreads();
        s[tid] += v;
        __syncthreads();
    }
    int i = blockIdx.x * blockDim.x + tid;
    if (i >= NN) return;
    int b = i / SCAN_B;
    int add = (b > 0) ? s[b - 1] : 0;
    int excl = add + g_scani[i] - g_cnt[i];
    g_off[i] = excl;
    g_cur[i] = excl;
}

// CSR fill: weight packed once as half2{w,w}
__global__ void k_fill(const void* __restrict__ ei, const float* __restrict__ ew) {
    int e = blockIdx.x * blockDim.x + threadIdx.x;
    if (e >= NE) return;
    int r = ldidx(ei, e);
    int c = ldidx(ei, (long long)NE + e);
    int p = atomicAdd(&g_cur[c], 1);
    float w = ew[e];
    __half2 wp = __floats2half2_rn(w, w);
    g_csr[p] = make_int2(r, *reinterpret_cast<int*>(&wp));
}

// warp per node: deg = coalesced bucket sum, dinv, prescale x.
__global__ void k_prep(const float* __restrict__ x) {
    int t = blockIdx.x * blockDim.x + threadIdx.x;
    int i = t >> 5, lane = t & 31;
    if (i >= NN) return;
    int beg = g_off[i];
    int cnt = g_cnt[i];
    float s = 0.f;
    for (int e = lane; e < cnt; e += 32) {
        int wb = g_csr[beg + e].y;
        s += __low2float(*reinterpret_cast<__half2*>(&wb));
    }
#pragma unroll
    for (int d = 1; d < 32; d <<= 1)
        s += __shfl_xor_sync(0xffffffffu, s, d);
    float dv = rsqrtf(s + 1.0f);
    if (lane == 0) {
        g_deg[i] = dv;
        float4 xi = __ldg(&reinterpret_cast<const float4*>(x)[i]);
        g_x[i] = make_float4(dv * xi.x, dv * xi.y, dv * xi.z, dv * xi.w);
    }
}

// Layer 1: gather prescaled 16B fp32 x rows (lane-strided);
// h1 = relu(dv*(sum+self)@W1+b1); store g_Bh[i] = fp16(dv * (h1@W2)).
__global__ void k_layer1(const float* __restrict__ W1, const float* __restrict__ b1,
                         const float* __restrict__ W2) {
    __shared__ float W1s[4 * HD];
    __shared__ float W2s[HD * HD];
    int tid = threadIdx.x;
    for (int k = tid; k < 4 * HD; k += blockDim.x)  W1s[k] = W1[k];
    for (int k = tid; k < HD * HD; k += blockDim.x) W2s[k] = W2[k];
    __syncthreads();
    int t = blockIdx.x * blockDim.x + tid;
    int i = t >> 5, lane = t & 31;
    if (i >= NN) return;

    int beg = g_off[i];
    int cnt = g_cnt[i];
    float4 acc = make_float4(0.f, 0.f, 0.f, 0.f);
    for (int e = lane; e < cnt; e += 32) {
        int2 ce = g_csr[beg + e];
        float w = __low2float(*reinterpret_cast<__half2*>(&ce.y));
        float4 xv = g_x[ce.x];
        acc.x = fmaf(w, xv.x, acc.x);
        acc.y = fmaf(w, xv.y, acc.y);
        acc.z = fmaf(w, xv.z, acc.z);
        acc.w = fmaf(w, xv.w, acc.w);
    }
#pragma unroll
    for (int d = 1; d < 32; d <<= 1) {
        acc.x += __shfl_xor_sync(0xffffffffu, acc.x, d);
        acc.y += __shfl_xor_sync(0xffffffffu, acc.y, d);
        acc.z += __shfl_xor_sync(0xffffffffu, acc.z, d);
        acc.w += __shfl_xor_sync(0xffffffffu, acc.w, d);
    }
    float4 xi = g_x[i];
    float dv = g_deg[i];
    acc.x = (acc.x + xi.x) * dv;
    acc.y = (acc.y + xi.y) * dv;
    acc.z = (acc.z + xi.z) * dv;
    acc.w = (acc.w + xi.w) * dv;

    float h = __ldg(&b1[lane]);
    h = fmaf(acc.x, W1s[0 * HD + lane], h);
    h = fmaf(acc.y, W1s[1 * HD + lane], h);
    h = fmaf(acc.z, W1s[2 * HD + lane], h);
    h = fmaf(acc.w, W1s[3 * HD + lane], h);
    h = fmaxf(h, 0.f);

    float o = 0.f;
#pragma unroll
    for (int k = 0; k < HD; k++) {
        float hk = __shfl_sync(0xffffffffu, h, k);
        o = fmaf(hk, W2s[k * HD + lane], o);
    }
    g_Bh[(size_t)i * HD + lane] = __float2half_rn(dv * o);
}

// HFMA2 fp16 gather (R13 best form): warp = 4 edge-groups x 8 lanes, 8 edges/iter.
__device__ __forceinline__ float4 gather_node_h2(const uint2* __restrict__ src, int i,
                                                 int grp, int sub) {
    int beg = g_off[i];
    int cnt = g_cnt[i];
    const __half2 hz = __floats2half2_rn(0.f, 0.f);
    __half2 a01 = hz, a23 = hz, b01 = hz, b23 = hz;
    int e = 0;
#pragma unroll 2
    for (; e + 8 <= cnt; e += 8) {
        int2 ce0 = g_csr[beg + e + grp];
        int2 ce1 = g_csr[beg + e + 4 + grp];
        __half2 w0 = *reinterpret_cast<__half2*>(&ce0.y);
        __half2 w1 = *reinterpret_cast<__half2*>(&ce1.y);
        uint2 u0 = src[(size_t)ce0.x * 8 + sub];
        uint2 u1 = src[(size_t)ce1.x * 8 + sub];
        a01 = __hfma2(w0, *reinterpret_cast<__half2*>(&u0.x), a01);
        a23 = __hfma2(w0, *reinterpret_cast<__half2*>(&u0.y), a23);
        b01 = __hfma2(w1, *reinterpret_cast<__half2*>(&u1.x), b01);
        b23 = __hfma2(w1, *reinterpret_cast<__half2*>(&u1.y), b23);
    }
    if (e + 4 <= cnt) {
        int2 ce = g_csr[beg + e + grp];
        __half2 w = *reinterpret_cast<__half2*>(&ce.y);
        uint2 u = src[(size_t)ce.x * 8 + sub];
        a01 = __hfma2(w, *reinterpret_cast<__half2*>(&u.x), a01);
        a23 = __hfma2(w, *reinterpret_cast<__half2*>(&u.y), a23);
        e += 4;
    }
    int rem = cnt - e;                           // 0..3
    if (rem > 0) {
        int g2 = min(grp, rem - 1);              // clamp: valid load, zero weight
        int2 ce = g_csr[beg + e + g2];
        int wb = (grp < rem) ? ce.y : 0;
        __half2 w = *reinterpret_cast<__half2*>(&wb);
        uint2 u = src[(size_t)ce.x * 8 + sub];
        a01 = __hfma2(w, *reinterpret_cast<__half2*>(&u.x), a01);
        a23 = __hfma2(w, *reinterpret_cast<__half2*>(&u.y), a23);
    }
    float2 fa01 = __half22float2(a01), fa23 = __half22float2(a23);
    float2 fb01 = __half22float2(b01), fb23 = __half22float2(b23);
    float4 acc = make_float4(fa01.x + fb01.x, fa01.y + fb01.y,
                             fa23.x + fb23.x, fa23.y + fb23.y);
#pragma unroll
    for (int d = 8; d <= 16; d <<= 1) {          // reduce across the 4 groups
        acc.x += __shfl_xor_sync(0xffffffffu, acc.x, d);
        acc.y += __shfl_xor_sync(0xffffffffu, acc.y, d);
        acc.z += __shfl_xor_sync(0xffffffffu, acc.z, d);
        acc.w += __shfl_xor_sync(0xffffffffu, acc.w, d);
    }
    uint2 us = src[(size_t)i * 8 + sub];         // self row (prescaled)
    float2 s01 = __half22float2(*reinterpret_cast<__half2*>(&us.x));
    float2 s23 = __half22float2(*reinterpret_cast<__half2*>(&us.y));
    acc.x += s01.x; acc.y += s01.y; acc.z += s23.x; acc.w += s23.y;
    return acc;
}

// Layer 2: gather g_Bh; v = relu(dv*acc + b2); project to 3 dims with
// precomputed M (staged from g_M); store g_P[i] = float4{dv*(v@M), 0}.
__global__ void k_layer2(const float* __restrict__ bias) {
    __shared__ float Ms[HD * 3];
    int tid = threadIdx.x;
    if (tid < HD * 3) Ms[tid] = g_M[tid];
    __syncthreads();
    int t = blockIdx.x * blockDim.x + tid;
    int i = t >> 5, lane = t & 31, grp = lane >> 3, sub = lane & 7;
    if (i >= NN) return;

    float4 v = gather_node_h2(reinterpret_cast<const uint2*>(g_Bh), i, grp, sub);
    float dv = g_deg[i];
    float4 b4 = __ldg(&reinterpret_cast<const float4*>(bias)[sub]);
    v.x = fmaxf(fmaf(v.x, dv, b4.x), 0.f);
    v.y = fmaxf(fmaf(v.y, dv, b4.y), 0.f);
    v.z = fmaxf(fmaf(v.z, dv, b4.z), 0.f);
    v.w = fmaxf(fmaf(v.w, dv, b4.w), 0.f);

    // o_j = sum_k v_k * M[k][j]; lane holds k = 4*sub .. 4*sub+3
    float o0 = 0.f, o1 = 0.f, o2 = 0.f;
    int k0 = sub * 4;
    o0 = fmaf(v.x, Ms[(k0 + 0) * 3 + 0], o0);
    o1 = fmaf(v.x, Ms[(k0 + 0) * 3 + 1], o1);
    o2 = fmaf(v.x, Ms[(k0 + 0) * 3 + 2], o2);
    o0 = fmaf(v.y, Ms[(k0 + 1) * 3 + 0], o0);
    o1 = fmaf(v.y, Ms[(k0 + 1) * 3 + 1], o1);
    o2 = fmaf(v.y, Ms[(k0 + 1) * 3 + 2], o2);
    o0 = fmaf(v.z, Ms[(k0 + 2) * 3 + 0], o0);
    o1 = fmaf(v.z, Ms[(k0 + 2) * 3 + 1], o1);
    o2 = fmaf(v.z, Ms[(k0 + 2) * 3 + 2], o2);
    o0 = fmaf(v.w, Ms[(k0 + 3) * 3 + 0], o0);
    o1 = fmaf(v.w, Ms[(k0 + 3) * 3 + 1], o1);
    o2 = fmaf(v.w, Ms[(k0 + 3) * 3 + 2], o2);
#pragma unroll
    for (int d = 1; d <= 4; d <<= 1) {            // reduce across the 8 sub lanes
        o0 += __shfl_xor_sync(0xffffffffu, o0, d);
        o1 += __shfl_xor_sync(0xffffffffu, o1, d);
        o2 += __shfl_xor_sync(0xffffffffu, o2, d);
    }
    if (lane == 0)
        g_P[i] = make_float4(dv * o0, dv * o1, dv * o2, 0.f);
}

// Layer 3: lane-per-edge gather of 16B P rows + sorted-batch mean-pool (3 dims).
__global__ void k_gather_pool(const void* __restrict__ batch) {
    __shared__ float s[8][4];
    __shared__ int sg[8];
    int tid = threadIdx.x;
    int t = blockIdx.x * blockDim.x + tid;
    int i = t >> 5, lane = t & 31;
    int warpid = tid >> 5;
    int beg = g_off[i];
    int cnt = g_cnt[i];
    float a0 = 0.f, a1 = 0.f, a2 = 0.f;
    for (int e = lane; e < cnt; e += 32) {
        int2 ce = g_csr[beg + e];
        float w = __low2float(*reinterpret_cast<__half2*>(&ce.y));
        float4 p = g_P[ce.x];
        a0 = fmaf(w, p.x, a0);
        a1 = fmaf(w, p.y, a1);
        a2 = fmaf(w, p.z, a2);
    }
#pragma unroll
    for (int d = 1; d < 32; d <<= 1) {
        a0 += __shfl_xor_sync(0xffffffffu, a0, d);
        a1 += __shfl_xor_sync(0xffffffffu, a1, d);
        a2 += __shfl_xor_sync(0xffffffffu, a2, d);
    }
    if (lane == 0) {
        float4 pi = g_P[i];
        float dv = g_deg[i];
        s[warpid][0] = dv * (a0 + pi.x);
        s[warpid][1] = dv * (a1 + pi.y);
        s[warpid][2] = dv * (a2 + pi.z);
        sg[warpid] = ldidx(batch, i);
    }
    __syncthreads();
    if (tid < 3) {
        int g0 = sg[0];
        if (g0 == sg[7]) {                        // sorted => all 8 equal
            float sum = 0.f;
#pragma unroll
            for (int w = 0; w < 8; w++) sum += s[w][tid];
            atomicAdd(&g_gsum[g0 * 4 + tid], sum);
            if (tid == 0) atomicAdd(&g_gcnt[g0], 8.0f);
        } else {
#pragma unroll
            for (int w = 0; w < 8; w++)
                atomicAdd(&g_gsum[sg[w] * 4 + tid], s[w][tid]);
            if (tid == 0) {
#pragma unroll
                for (int w = 0; w < 8; w++) atomicAdd(&g_gcnt[sg[w]], 1.0f);
            }
        }
    }
}

// Head: logits_j = gsum_j/cnt + c_j with c = b3@lin_w + lin_b; softmax.
__global__ void k_head(const float* __restrict__ b3, const float* __restrict__ lw,
                       const float* __restrict__ lb, float* __restrict__ out) {
    int g = blockIdx.x * blockDim.x + threadIdx.x;
    if (g >= NG) return;
    float c0 = __ldg(&lb[0]), c1 = __ldg(&lb[1]), c2 = __ldg(&lb[2]);
#pragma unroll
    for (int f = 0; f < HD; f++) {
        float bf = __ldg(&b3[f]);
        c0 = fmaf(bf, __ldg(&lw[f * 3 + 0]), c0);
        c1 = fmaf(bf, __ldg(&lw[f * 3 + 1]), c1);
        c2 = fmaf(bf, __ldg(&lw[f * 3 + 2]), c2);
    }
    float inv = 1.0f / fmaxf(g_gcnt[g], 1.0f);
    float l0 = g_gsum[g * 4 + 0] * inv + c0;
    float l1 = g_gsum[g * 4 + 1] * inv + c1;
    float l2 = g_gsum[g * 4 + 2] * inv + c2;
    float m = fmaxf(l0, fmaxf(l1, l2));
    float e0 = expf(l0 - m), e1 = expf(l1 - m), e2 = expf(l2 - m);
    float s = 1.0f / (e0 + e1 + e2);
    out[g * 3 + 0] = e0 * s;
    out[g * 3 + 1] = e1 * s;
    out[g * 3 + 2] = e2 * s;
}

extern "C" void kernel_launch(void* const* d_in, const int* in_sizes, int n_in,
                              void* d_out, int out_size) {
    const float* x     = (const float*)d_in[0];
    const void*  ei    = d_in[1];
    const float* ew    = (const float*)d_in[2];
    const void*  batch = d_in[3];
    const float* W1    = (const float*)d_in[4];
    const float* b1    = (const float*)d_in[5];
    const float* W2    = (const float*)d_in[6];
    const float* b2    = (const float*)d_in[7];
    const float* W3    = (const float*)d_in[8];
    const float* b3    = (const float*)d_in[9];
    const float* lw    = (const float*)d_in[10];
    const float* lb    = (const float*)d_in[11];
    float* out = (float*)d_out;

    const int B = 256;
    const int gbN  = (NN + B - 1) / B;
    const int gbE  = (NE + B - 1) / B;
    const int gbNH = (NN * HD) / B;           // 12500 blocks, 8 nodes each

    k_init<<<gbN, B>>>(ei, W3, lw);           // + one-time M = W3@lin_w
    k_hist<<<gbE, B>>>(ei);
    k_scan1<<<NB, SCAN_B>>>();
    k_scan23<<<gbN, B>>>();
    k_fill<<<gbE, B>>>(ei, ew);
    k_prep<<<gbNH, B>>>(x);

    k_layer1<<<gbNH, B>>>(W1, b1, W2);        // gather g_x -> g_Bh (fp16)
    k_layer2<<<gbNH, B>>>(b2);                // gather g_Bh -> g_P (3-dim, fp32)
    k_gather_pool<<<gbNH, B>>>(batch);        // 16B-row gather g_P + pool
    k_head<<<(NG + B - 1) / B, B>>>(b3, lw, lb, out);
}

// round 17
// speedup vs baseline: 1.2736x; 1.0230x over previous
#include <cuda_runtime.h>
#include <cuda_fp16.h>

#define NN 100000
#define NE 2500000
#define NG 1000
#define HD 32
#define SCAN_B 512
#define NB ((NN + SCAN_B - 1) / SCAN_B)   // 196

// ---- scratch (__device__ globals; allocation-free) ----
__device__ int   g_is64;
__device__ __align__(16) float  g_M[HD * 3];      // W3 @ lin_w (one-time, k_init)
__device__ __align__(16) float  g_c[4];           // b3 @ lin_w + lin_b (one-time)
__device__ __align__(16) float  g_deg[NN];        // wdeg -> dinv (in place)
__device__ __align__(16) int    g_cnt[NN];
__device__ __align__(16) int    g_scani[NN];
__device__ __align__(16) int    g_bsum[256];
__device__ __align__(16) int    g_off[NN];
__device__ __align__(16) int    g_cur[NN];
__device__ __align__(16) int2   g_csr[NE];        // {src, packed half2{w,w}}
__device__ __align__(16) float4 g_x[NN];          // dinv[i] * x[i]
__device__ __align__(16) __half g_Bh[NN * HD];    // fp16 prescaled h1@W2
__device__ __align__(16) float4 g_P[NN];          // dv_i * (relu(h2)@M), 3 used
__device__ __align__(16) float  g_gsum[NG * 4];   // pooled 3-dim sums (padded 4)
__device__ __align__(16) float  g_gcnt[NG];

__device__ __forceinline__ int ldidx(const void* p, long long e) {
    if (g_is64) return (int)((const long long*)p)[e];
    return ((const int*)p)[e];
}

// init + index-width detect + one-time M = W3@lin_w and c = b3@lin_w + lin_b
__global__ void k_init(const void* ei, const float* __restrict__ W3,
                       const float* __restrict__ lw, const float* __restrict__ b3,
                       const float* __restrict__ lb) {
    int t = blockIdx.x * blockDim.x + threadIdx.x;
    if (t == 0) {
        const int* p = (const int*)ei;
        int z = 0;
#pragma unroll
        for (int j = 1; j < 64; j += 2) z |= p[j];
        g_is64 = (z == 0) ? 1 : 0;
    }
    if (blockIdx.x == 0 && threadIdx.x < HD * 3) {
        int k = threadIdx.x / 3, j = threadIdx.x % 3;
        float m = 0.f;
#pragma unroll
        for (int f = 0; f < HD; f++)
            m = fmaf(__ldg(&W3[k * HD + f]), __ldg(&lw[f * 3 + j]), m);
        g_M[threadIdx.x] = m;
    }
    if (blockIdx.x == 0 && threadIdx.x >= HD * 3 && threadIdx.x < HD * 3 + 3) {
        int j = threadIdx.x - HD * 3;
        float c = __ldg(&lb[j]);
#pragma unroll
        for (int f = 0; f < HD; f++)
            c = fmaf(__ldg(&b3[f]), __ldg(&lw[f * 3 + j]), c);
        g_c[j] = c;
    }
    if (t < NN) { g_cnt[t] = 0; g_deg[t] = 0.f; }
    if (t < NG * 4) g_gsum[t] = 0.f;
    if (t < NG) g_gcnt[t] = 0.f;
}

// histogram + fp32 weighted degree (one pass over col half + ew)
__global__ void k_hist(const void* __restrict__ ei, const float* __restrict__ ew) {
    int e = blockIdx.x * blockDim.x + threadIdx.x;
    if (e >= NE) return;
    int c = ldidx(ei, (long long)NE + e);
    atomicAdd(&g_cnt[c], 1);
    atomicAdd(&g_deg[c], ew[e]);
}

__global__ void k_scan1() {
    __shared__ int s[SCAN_B];
    int tid = threadIdx.x;
    int i = blockIdx.x * SCAN_B + tid;
    s[tid] = (i < NN) ? g_cnt[i] : 0;
    __syncthreads();
#pragma unroll
    for (int off = 1; off < SCAN_B; off <<= 1) {
        int v = (tid >= off) ? s[tid - off] : 0;
        __syncthreads();
        s[tid] += v;
        __syncthreads();
    }
    if (i < NN) g_scani[i] = s[tid];
    if (tid == SCAN_B - 1) g_bsum[blockIdx.x] = s[tid];
}

// merged scan2+scan3 + dinv + x prescale (deletes the old k_prep)
__global__ void k_scan23(const float* __restrict__ x) {
    __shared__ int s[256];
    int tid = threadIdx.x;
    s[tid] = (tid < NB) ? g_bsum[tid] : 0;
    __syncthreads();
#pragma unroll
    for (int off = 1; off < 256; off <<= 1) {
        int v = (tid >= off) ? s[tid - off] : 0;
        __syncthreads();
        s[tid] += v;
        __syncthreads();
    }
    int i = blockIdx.x * blockDim.x + tid;
    if (i >= NN) return;
    int b = i / SCAN_B;
    int add = (b > 0) ? s[b - 1] : 0;
    int excl = add + g_scani[i] - g_cnt[i];
    g_off[i] = excl;
    g_cur[i] = excl;
    float dv = rsqrtf(g_deg[i] + 1.0f);   // +1 = self-loop weight
    g_deg[i] = dv;
    float4 xi = __ldg(&reinterpret_cast<const float4*>(x)[i]);
    g_x[i] = make_float4(dv * xi.x, dv * xi.y, dv * xi.z, dv * xi.w);
}

// CSR fill: weight packed once as half2{w,w}
__global__ void k_fill(const void* __restrict__ ei, const float* __restrict__ ew) {
    int e = blockIdx.x * blockDim.x + threadIdx.x;
    if (e >= NE) return;
    int r = ldidx(ei, e);
    int c = ldidx(ei, (long long)NE + e);
    int p = atomicAdd(&g_cur[c], 1);
    float w = ew[e];
    __half2 wp = __floats2half2_rn(w, w);
    g_csr[p] = make_int2(r, *reinterpret_cast<int*>(&wp));
}

// Layer 1: gather prescaled 16B fp32 x rows (lane-strided);
// h1 = relu(dv*(sum+self)@W1+b1); store g_Bh[i] = fp16(dv * (h1@W2)).
__global__ void k_layer1(const float* __restrict__ W1, const float* __restrict__ b1,
                         const float* __restrict__ W2) {
    __shared__ float W1s[4 * HD];
    __shared__ float W2s[HD * HD];
    int tid = threadIdx.x;
    for (int k = tid; k < 4 * HD; k += blockDim.x)  W1s[k] = W1[k];
    for (int k = tid; k < HD * HD; k += blockDim.x) W2s[k] = W2[k];
    __syncthreads();
    int t = blockIdx.x * blockDim.x + tid;
    int i = t >> 5, lane = t & 31;
    if (i >= NN) return;

    int beg = g_off[i];
    int cnt = g_cnt[i];
    float4 acc = make_float4(0.f, 0.f, 0.f, 0.f);
    for (int e = lane; e < cnt; e += 32) {
        int2 ce = g_csr[beg + e];
        float w = __low2float(*reinterpret_cast<__half2*>(&ce.y));
        float4 xv = g_x[ce.x];
        acc.x = fmaf(w, xv.x, acc.x);
        acc.y = fmaf(w, xv.y, acc.y);
        acc.z = fmaf(w, xv.z, acc.z);
        acc.w = fmaf(w, xv.w, acc.w);
    }
#pragma unroll
    for (int d = 1; d < 32; d <<= 1) {
        acc.x += __shfl_xor_sync(0xffffffffu, acc.x, d);
        acc.y += __shfl_xor_sync(0xffffffffu, acc.y, d);
        acc.z += __shfl_xor_sync(0xffffffffu, acc.z, d);
        acc.w += __shfl_xor_sync(0xffffffffu, acc.w, d);
    }
    float4 xi = g_x[i];
    float dv = g_deg[i];
    acc.x = (acc.x + xi.x) * dv;
    acc.y = (acc.y + xi.y) * dv;
    acc.z = (acc.z + xi.z) * dv;
    acc.w = (acc.w + xi.w) * dv;

    float h = __ldg(&b1[lane]);
    h = fmaf(acc.x, W1s[0 * HD + lane], h);
    h = fmaf(acc.y, W1s[1 * HD + lane], h);
    h = fmaf(acc.z, W1s[2 * HD + lane], h);
    h = fmaf(acc.w, W1s[3 * HD + lane], h);
    h = fmaxf(h, 0.f);

    float o = 0.f;
#pragma unroll
    for (int k = 0; k < HD; k++) {
        float hk = __shfl_sync(0xffffffffu, h, k);
        o = fmaf(hk, W2s[k * HD + lane], o);
    }
    g_Bh[(size_t)i * HD + lane] = __float2half_rn(dv * o);
}

// HFMA2 fp16 gather (best form): warp = 4 edge-groups x 8 lanes, 8 edges/iter.
__device__ __forceinline__ float4 gather_node_h2(const uint2* __restrict__ src, int i,
                                                 int grp, int sub) {
    int beg = g_off[i];
    int cnt = g_cnt[i];
    const __half2 hz = __floats2half2_rn(0.f, 0.f);
    __half2 a01 = hz, a23 = hz, b01 = hz, b23 = hz;
    int e = 0;
#pragma unroll 2
    for (; e + 8 <= cnt; e += 8) {
        int2 ce0 = g_csr[beg + e + grp];
        int2 ce1 = g_csr[beg + e + 4 + grp];
        __half2 w0 = *reinterpret_cast<__half2*>(&ce0.y);
        __half2 w1 = *reinterpret_cast<__half2*>(&ce1.y);
        uint2 u0 = src[(size_t)ce0.x * 8 + sub];
        uint2 u1 = src[(size_t)ce1.x * 8 + sub];
        a01 = __hfma2(w0, *reinterpret_cast<__half2*>(&u0.x), a01);
        a23 = __hfma2(w0, *reinterpret_cast<__half2*>(&u0.y), a23);
        b01 = __hfma2(w1, *reinterpret_cast<__half2*>(&u1.x), b01);
        b23 = __hfma2(w1, *reinterpret_cast<__half2*>(&u1.y), b23);
    }
    if (e + 4 <= cnt) {
        int2 ce = g_csr[beg + e + grp];
        __half2 w = *reinterpret_cast<__half2*>(&ce.y);
        uint2 u = src[(size_t)ce.x * 8 + sub];
        a01 = __hfma2(w, *reinterpret_cast<__half2*>(&u.x), a01);
        a23 = __hfma2(w, *reinterpret_cast<__half2*>(&u.y), a23);
        e += 4;
    }
    int rem = cnt - e;                           // 0..3
    if (rem > 0) {
        int g2 = min(grp, rem - 1);              // clamp: valid load, zero weight
        int2 ce = g_csr[beg + e + g2];
        int wb = (grp < rem) ? ce.y : 0;
        __half2 w = *reinterpret_cast<__half2*>(&wb);
        uint2 u = src[(size_t)ce.x * 8 + sub];
        a01 = __hfma2(w, *reinterpret_cast<__half2*>(&u.x), a01);
        a23 = __hfma2(w, *reinterpret_cast<__half2*>(&u.y), a23);
    }
    float2 fa01 = __half22float2(a01), fa23 = __half22float2(a23);
    float2 fb01 = __half22float2(b01), fb23 = __half22float2(b23);
    float4 acc = make_float4(fa01.x + fb01.x, fa01.y + fb01.y,
                             fa23.x + fb23.x, fa23.y + fb23.y);
#pragma unroll
    for (int d = 8; d <= 16; d <<= 1) {          // reduce across the 4 groups
        acc.x += __shfl_xor_sync(0xffffffffu, acc.x, d);
        acc.y += __shfl_xor_sync(0xffffffffu, acc.y, d);
        acc.z += __shfl_xor_sync(0xffffffffu, acc.z, d);
        acc.w += __shfl_xor_sync(0xffffffffu, acc.w, d);
    }
    uint2 us = src[(size_t)i * 8 + sub];         // self row (prescaled)
    float2 s01 = __half22float2(*reinterpret_cast<__half2*>(&us.x));
    float2 s23 = __half22float2(*reinterpret_cast<__half2*>(&us.y));
    acc.x += s01.x; acc.y += s01.y; acc.z += s23.x; acc.w += s23.y;
    return acc;
}

// Layer 2: gather g_Bh; v = relu(dv*acc + b2); project to 3 dims with
// precomputed M; store g_P[i] = float4{dv*(v@M), 0}.
__global__ void k_layer2(const float* __restrict__ bias) {
    __shared__ float Ms[HD * 3];
    int tid = threadIdx.x;
    if (tid < HD * 3) Ms[tid] = g_M[tid];
    __syncthreads();
    int t = blockIdx.x * blockDim.x + tid;
    int i = t >> 5, lane = t & 31, grp = lane >> 3, sub = lane & 7;
    if (i >= NN) return;

    float4 v = gather_node_h2(reinterpret_cast<const uint2*>(g_Bh), i, grp, sub);
    float dv = g_deg[i];
    float4 b4 = __ldg(&reinterpret_cast<const float4*>(bias)[sub]);
    v.x = fmaxf(fmaf(v.x, dv, b4.x), 0.f);
    v.y = fmaxf(fmaf(v.y, dv, b4.y), 0.f);
    v.z = fmaxf(fmaf(v.z, dv, b4.z), 0.f);
    v.w = fmaxf(fmaf(v.w, dv, b4.w), 0.f);

    float o0 = 0.f, o1 = 0.f, o2 = 0.f;
    int k0 = sub * 4;
    o0 = fmaf(v.x, Ms[(k0 + 0) * 3 + 0], o0);
    o1 = fmaf(v.x, Ms[(k0 + 0) * 3 + 1], o1);
    o2 = fmaf(v.x, Ms[(k0 + 0) * 3 + 2], o2);
    o0 = fmaf(v.y, Ms[(k0 + 1) * 3 + 0], o0);
    o1 = fmaf(v.y, Ms[(k0 + 1) * 3 + 1], o1);
    o2 = fmaf(v.y, Ms[(k0 + 1) * 3 + 2], o2);
    o0 = fmaf(v.z, Ms[(k0 + 2) * 3 + 0], o0);
    o1 = fmaf(v.z, Ms[(k0 + 2) * 3 + 1], o1);
    o2 = fmaf(v.z, Ms[(k0 + 2) * 3 + 2], o2);
    o0 = fmaf(v.w, Ms[(k0 + 3) * 3 + 0], o0);
    o1 = fmaf(v.w, Ms[(k0 + 3) * 3 + 1], o1);
    o2 = fmaf(v.w, Ms[(k0 + 3) * 3 + 2], o2);
#pragma unroll
    for (int d = 1; d <= 4; d <<= 1) {            // reduce across the 8 sub lanes
        o0 += __shfl_xor_sync(0xffffffffu, o0, d);
        o1 += __shfl_xor_sync(0xffffffffu, o1, d);
        o2 += __shfl_xor_sync(0xffffffffu, o2, d);
    }
    if (lane == 0)
        g_P[i] = make_float4(dv * o0, dv * o1, dv * o2, 0.f);
}

// Layer 3: lane-per-edge gather of 16B P rows + sorted-batch mean-pool (3 dims).
__global__ void k_gather_pool(const void* __restrict__ batch) {
    __shared__ float s[8][4];
    __shared__ int sg[8];
    int tid = threadIdx.x;
    int t = blockIdx.x * blockDim.x + tid;
    int i = t >> 5, lane = t & 31;
    int warpid = tid >> 5;
    int beg = g_off[i];
    int cnt = g_cnt[i];
    float a0 = 0.f, a1 = 0.f, a2 = 0.f;
    for (int e = lane; e < cnt; e += 32) {
        int2 ce = g_csr[beg + e];
        float w = __low2float(*reinterpret_cast<__half2*>(&ce.y));
        float4 p = g_P[ce.x];
        a0 = fmaf(w, p.x, a0);
        a1 = fmaf(w, p.y, a1);
        a2 = fmaf(w, p.z, a2);
    }
#pragma unroll
    for (int d = 1; d < 32; d <<= 1) {
        a0 += __shfl_xor_sync(0xffffffffu, a0, d);
        a1 += __shfl_xor_sync(0xffffffffu, a1, d);
        a2 += __shfl_xor_sync(0xffffffffu, a2, d);
    }
    if (lane == 0) {
        float4 pi = g_P[i];
        float dv = g_deg[i];
        s[warpid][0] = dv * (a0 + pi.x);
        s[warpid][1] = dv * (a1 + pi.y);
        s[warpid][2] = dv * (a2 + pi.z);
        sg[warpid] = ldidx(batch, i);
    }
    __syncthreads();
    if (tid < 3) {
        int g0 = sg[0];
        if (g0 == sg[7]) {                        // sorted => all 8 equal
            float sum = 0.f;
#pragma unroll
            for (int w = 0; w < 8; w++) sum += s[w][tid];
            atomicAdd(&g_gsum[g0 * 4 + tid], sum);
            if (tid == 0) atomicAdd(&g_gcnt[g0], 8.0f);
        } else {
#pragma unroll
            for (int w = 0; w < 8; w++)
                atomicAdd(&g_gsum[sg[w] * 4 + tid], s[w][tid]);
            if (tid == 0) {
#pragma unroll
                for (int w = 0; w < 8; w++) atomicAdd(&g_gcnt[sg[w]], 1.0f);
            }
        }
    }
}

// Head: logits_j = gsum_j/cnt + c_j (c precomputed in k_init); softmax.
__global__ void k_head(float* __restrict__ out) {
    int g = blockIdx.x * blockDim.x + threadIdx.x;
    if (g >= NG) return;
    float inv = 1.0f / fmaxf(g_gcnt[g], 1.0f);
    float l0 = g_gsum[g * 4 + 0] * inv + g_c[0];
    float l1 = g_gsum[g * 4 + 1] * inv + g_c[1];
    float l2 = g_gsum[g * 4 + 2] * inv + g_c[2];
    float m = fmaxf(l0, fmaxf(l1, l2));
    float e0 = expf(l0 - m), e1 = expf(l1 - m), e2 = expf(l2 - m);
    float s = 1.0f / (e0 + e1 + e2);
    out[g * 3 + 0] = e0 * s;
    out[g * 3 + 1] = e1 * s;
    out[g * 3 + 2] = e2 * s;
}

extern "C" void kernel_launch(void* const* d_in, const int* in_sizes, int n_in,
                              void* d_out, int out_size) {
    const float* x     = (const float*)d_in[0];
    const void*  ei    = d_in[1];
    const float* ew    = (const float*)d_in[2];
    const void*  batch = d_in[3];
    const float* W1    = (const float*)d_in[4];
    const float* b1    = (const float*)d_in[5];
    const float* W2    = (const float*)d_in[6];
    const float* b2    = (const float*)d_in[7];
    const float* W3    = (const float*)d_in[8];
    const float* b3    = (const float*)d_in[9];
    const float* lw    = (const float*)d_in[10];
    const float* lb    = (const float*)d_in[11];
    float* out = (float*)d_out;

    const int B = 256;
    const int gbN  = (NN + B - 1) / B;
    const int gbE  = (NE + B - 1) / B;
    const int gbNH = (NN * HD) / B;           // 12500 blocks, 8 nodes each

    k_init<<<gbN, B>>>(ei, W3, lw, b3, lb);   // + one-time M, c
    k_hist<<<gbE, B>>>(ei, ew);               // cnt + fp32 weighted degree
    k_scan1<<<NB, SCAN_B>>>();
    k_scan23<<<gbN, B>>>(x);                  // offsets + dinv + x prescale
    k_fill<<<gbE, B>>>(ei, ew);

    k_layer1<<<gbNH, B>>>(W1, b1, W2);        // gather g_x -> g_Bh (fp16)
    k_layer2<<<gbNH, B>>>(b2);                // gather g_Bh -> g_P (3-dim, fp32)
    k_gather_pool<<<gbNH, B>>>(batch);        // 16B-row gather g_P + pool
    k_head<<<(NG + B - 1) / B, B>>>(out);
}